// round 14
// baseline (speedup 1.0000x reference)
#include <cuda_runtime.h>
#include <cuda_bf16.h>
#include <cstdint>

#define IN_CH   256
#define OUT_CH  256
#define NTASKS  64
#define WSIZE   (OUT_CH * IN_CH)
#define FULL_EMBED (WSIZE + OUT_CH)
#define BMAX    4096
#define NCOLS   128             // output cols per CTA
#define MT      32              // rows per M-tile
#define THREADS 256

// bf16 row stride: 264 elements = 528 bytes (conflict-free ldmatrix phases)
#define RSTRIDE_B 528

// smem byte offsets
#define SM_WHI  0
#define SM_WLO  (SM_WHI + NCOLS * RSTRIDE_B)        // 67584
#define SM_XHI  (SM_WLO + NCOLS * RSTRIDE_B)        // 135168
#define SM_XLO  (SM_XHI + MT * RSTRIDE_B)           // 152064
#define SM_BIAS (SM_XLO + MT * RSTRIDE_B)           // 168960
#define SM_LIST (SM_BIAS + NCOLS * 4)               // 169472 (uint16 x 4096)
#define SM_CNT  (SM_LIST + BMAX * 2)                // 177664
#define SMEM_B  (SM_CNT + 16)                       // ~173.5KB, 1 CTA/SM

// ================= helpers =================================================
__device__ __forceinline__ uint32_t smem_u32(const void* p) {
    uint32_t a;
    asm("{ .reg .u64 t; cvta.to.shared.u64 t, %1; cvt.u32.u64 %0, t; }" : "=r"(a) : "l"(p));
    return a;
}
__device__ __forceinline__ uint32_t pack_bf16(float a, float b) {
    __nv_bfloat162 t = __floats2bfloat162_rn(a, b);
    return *(uint32_t*)&t;
}
__device__ __forceinline__ float bf_hi(float x) {
    return __bfloat162float(__float2bfloat16(x));
}

#define LDSM_X4(r0, r1, r2, r3, addr)                                      \
    asm volatile("ldmatrix.sync.aligned.m8n8.x4.shared.b16 {%0,%1,%2,%3}, [%4];" \
        : "=r"(r0), "=r"(r1), "=r"(r2), "=r"(r3) : "r"(addr))

#define MMA_BF16(c, a0, a1, a2, a3, b0, b1)                                \
    asm volatile("mma.sync.aligned.m16n8k16.row.col.f32.bf16.bf16.f32 "    \
        "{%0,%1,%2,%3}, {%4,%5,%6,%7}, {%8,%9}, {%0,%1,%2,%3};"            \
        : "+f"((c)[0]), "+f"((c)[1]), "+f"((c)[2]), "+f"((c)[3])           \
        : "r"(a0), "r"(a1), "r"(a2), "r"(a3), "r"(b0), "r"(b1))

// ================= main: CTA = (task, 128-col chunk), fused scan ===========
__global__ __launch_bounds__(THREADS, 1)
void affine_hmma_kernel(const float* __restrict__ inputs,
                        const int* __restrict__ task_ids,
                        const float* __restrict__ te,
                        float* __restrict__ out,
                        int B) {
    extern __shared__ char smem[];
    const uint32_t sb = smem_u32(smem);
    float* bias_sm = (float*)(smem + SM_BIAS);
    unsigned short* list = (unsigned short*)(smem + SM_LIST);
    int* s_n = (int*)(smem + SM_CNT);

    const int task    = blockIdx.y;
    const int colBase = blockIdx.x * NCOLS;
    const int tid     = threadIdx.x;
    const int lane    = tid & 31;
    const int wid     = tid >> 5;      // 0..7

    if (tid == 0) s_n[0] = 0;
    __syncthreads();

    const float* emb = te + (size_t)task * FULL_EMBED;

    // ---- issue first W batch (8 cols/warp) BEFORE the scan (latency hidden) ----
    // warp w covers cols {w, w+8, ..., w+120}; batch 1 = first 8 of those
    float4 wa0[8], wa1[8];
    #pragma unroll
    for (int rr = 0; rr < 8; rr++) {
        const int c = wid + rr * 8;                   // cols w .. w+56
        const float4* wg = (const float4*)(emb + (size_t)(colBase + c) * IN_CH);
        wa0[rr] = wg[lane];
        wa1[rr] = wg[lane + 32];
    }

    // ---- fused scan: warp-aggregated (1 atomic per warp iteration) ----
    #pragma unroll
    for (int i = tid; i < BMAX; i += THREADS) {
        const bool m = (i < B) && (task_ids[i] == task);
        const unsigned bal = __ballot_sync(0xFFFFFFFFu, m);
        if (bal) {
            int base = 0;
            if (lane == 0) base = atomicAdd(s_n, __popc(bal));
            base = __shfl_sync(0xFFFFFFFFu, base, 0);
            if (m) list[base + __popc(bal & ((1u << lane) - 1u))] = (unsigned short)i;
        }
    }

    // ---- stage bias ----
    if (tid < NCOLS) bias_sm[tid] = emb[WSIZE + colBase + tid];

    // ---- W batch 1 convert+STS, then batch 2 load/convert/STS ----
    #pragma unroll
    for (int rr = 0; rr < 8; rr++) {
        const int c = wid + rr * 8;
        char* whi = smem + SM_WHI + c * RSTRIDE_B;
        char* wlo = smem + SM_WLO + c * RSTRIDE_B;
        float4 a = wa0[rr], b = wa1[rr];
        *(uint2*)(whi + lane * 8) =
            make_uint2(pack_bf16(a.x, a.y), pack_bf16(a.z, a.w));
        *(uint2*)(whi + 256 + lane * 8) =
            make_uint2(pack_bf16(b.x, b.y), pack_bf16(b.z, b.w));
        *(uint2*)(wlo + lane * 8) =
            make_uint2(pack_bf16(a.x - bf_hi(a.x), a.y - bf_hi(a.y)),
                       pack_bf16(a.z - bf_hi(a.z), a.w - bf_hi(a.w)));
        *(uint2*)(wlo + 256 + lane * 8) =
            make_uint2(pack_bf16(b.x - bf_hi(b.x), b.y - bf_hi(b.y)),
                       pack_bf16(b.z - bf_hi(b.z), b.w - bf_hi(b.w)));
    }
    #pragma unroll
    for (int rr = 0; rr < 8; rr++) {
        const int c = wid + 64 + rr * 8;              // cols w+64 .. w+120
        const float4* wg = (const float4*)(emb + (size_t)(colBase + c) * IN_CH);
        wa0[rr] = wg[lane];
        wa1[rr] = wg[lane + 32];
    }
    #pragma unroll
    for (int rr = 0; rr < 8; rr++) {
        const int c = wid + 64 + rr * 8;
        char* whi = smem + SM_WHI + c * RSTRIDE_B;
        char* wlo = smem + SM_WLO + c * RSTRIDE_B;
        float4 a = wa0[rr], b = wa1[rr];
        *(uint2*)(whi + lane * 8) =
            make_uint2(pack_bf16(a.x, a.y), pack_bf16(a.z, a.w));
        *(uint2*)(whi + 256 + lane * 8) =
            make_uint2(pack_bf16(b.x, b.y), pack_bf16(b.z, b.w));
        *(uint2*)(wlo + lane * 8) =
            make_uint2(pack_bf16(a.x - bf_hi(a.x), a.y - bf_hi(a.y)),
                       pack_bf16(a.z - bf_hi(a.z), a.w - bf_hi(a.w)));
        *(uint2*)(wlo + 256 + lane * 8) =
            make_uint2(pack_bf16(b.x - bf_hi(b.x), b.y - bf_hi(b.y)),
                       pack_bf16(b.z - bf_hi(b.z), b.w - bf_hi(b.w)));
    }
    __syncthreads();
    const int n = s_n[0];

    // ---- warp tiling: 2 (M) x 4 (N); warp = m16 x n32 (R7-verified maps) ----
    const int warp_m = wid >> 2;          // 0..1
    const int warp_n = wid & 3;           // 0..3
    const int mrow0  = warp_m * 16;
    const int ncol0  = warp_n * 32;
    const int g      = lane >> 2;
    const int tg     = lane & 3;

    const int a_row  = mrow0 + ((lane >> 3) & 1) * 8 + (lane & 7);
    const uint32_t a_off = (uint32_t)a_row * RSTRIDE_B + ((lane >> 4) * 16);
    const int b_col0 = ncol0 + (lane >> 4) * 8 + (lane & 7);
    const uint32_t b_koff = ((lane >> 3) & 1) * 16;
    const uint32_t bh0 = sb + SM_WHI + (uint32_t)b_col0 * RSTRIDE_B + b_koff;
    const uint32_t bh1 = bh0 + 16 * RSTRIDE_B;
    const uint32_t bl0 = bh0 + (SM_WLO - SM_WHI);
    const uint32_t bl1 = bh1 + (SM_WLO - SM_WHI);
    const uint32_t ahi = sb + SM_XHI + a_off;
    const uint32_t alo = sb + SM_XLO + a_off;

    // ---- X prefetch registers: 4 rows per warp per tile ----
    float4 v0[4], v1[4];
    // pre-load tile 0
    #pragma unroll
    for (int rr = 0; rr < 4; rr++) {
        const int row = wid * 4 + rr;
        if (row < n) {
            const float4* xg = (const float4*)(inputs + (size_t)list[row] * IN_CH);
            v0[rr] = xg[lane];
            v1[rr] = xg[lane + 32];
        }
    }

    // ---- loop over 32-row tiles (X prefetched one tile ahead) ----
    for (int m0 = 0; m0 < n; m0 += MT) {
        // STS this tile's X (valid rows only; stale rows masked by epilogue)
        {
            const int nv = min(4, n - (m0 + wid * 4));
            for (int rr = 0; rr < nv; rr++) {
                const int r = wid * 4 + rr;
                char* xhi = smem + SM_XHI + r * RSTRIDE_B;
                char* xlo = smem + SM_XLO + r * RSTRIDE_B;
                float4 a = v0[rr], b = v1[rr];
                *(uint2*)(xhi + lane * 8) =
                    make_uint2(pack_bf16(a.x, a.y), pack_bf16(a.z, a.w));
                *(uint2*)(xhi + 256 + lane * 8) =
                    make_uint2(pack_bf16(b.x, b.y), pack_bf16(b.z, b.w));
                *(uint2*)(xlo + lane * 8) =
                    make_uint2(pack_bf16(a.x - bf_hi(a.x), a.y - bf_hi(a.y)),
                               pack_bf16(a.z - bf_hi(a.z), a.w - bf_hi(a.w)));
                *(uint2*)(xlo + 256 + lane * 8) =
                    make_uint2(pack_bf16(b.x - bf_hi(b.x), b.y - bf_hi(b.y)),
                               pack_bf16(b.z - bf_hi(b.z), b.w - bf_hi(b.w)));
            }
        }
        __syncthreads();

        // prefetch next tile's X (overlaps the k-loop below)
        #pragma unroll
        for (int rr = 0; rr < 4; rr++) {
            const int row = m0 + MT + wid * 4 + rr;
            if (row < n) {
                const float4* xg = (const float4*)(inputs + (size_t)list[row] * IN_CH);
                v0[rr] = xg[lane];
                v1[rr] = xg[lane + 32];
            }
        }

        if (m0 + mrow0 < n) {
            float acc[4][4];
            #pragma unroll
            for (int f = 0; f < 4; f++)
                #pragma unroll
                for (int j = 0; j < 4; j++) acc[f][j] = 0.f;

            #pragma unroll 4
            for (int ks = 0; ks < IN_CH; ks += 16) {
                const uint32_t kb = ks * 2;
                uint32_t aH0, aH1, aH2, aH3, aL0, aL1, aL2, aL3;
                uint32_t h00, h01, h02, h03, h10, h11, h12, h13;
                uint32_t l00, l01, l02, l03, l10, l11, l12, l13;
                LDSM_X4(aH0, aH1, aH2, aH3, ahi + kb);
                LDSM_X4(aL0, aL1, aL2, aL3, alo + kb);
                LDSM_X4(h00, h01, h02, h03, bh0 + kb);
                LDSM_X4(h10, h11, h12, h13, bh1 + kb);
                LDSM_X4(l00, l01, l02, l03, bl0 + kb);
                LDSM_X4(l10, l11, l12, l13, bl1 + kb);
                MMA_BF16(acc[0], aH0, aH1, aH2, aH3, h00, h01);
                MMA_BF16(acc[1], aH0, aH1, aH2, aH3, h02, h03);
                MMA_BF16(acc[2], aH0, aH1, aH2, aH3, h10, h11);
                MMA_BF16(acc[3], aH0, aH1, aH2, aH3, h12, h13);
                MMA_BF16(acc[0], aH0, aH1, aH2, aH3, l00, l01);
                MMA_BF16(acc[1], aH0, aH1, aH2, aH3, l02, l03);
                MMA_BF16(acc[2], aH0, aH1, aH2, aH3, l10, l11);
                MMA_BF16(acc[3], aH0, aH1, aH2, aH3, l12, l13);
                MMA_BF16(acc[0], aL0, aL1, aL2, aL3, h00, h01);
                MMA_BF16(acc[1], aL0, aL1, aL2, aL3, h02, h03);
                MMA_BF16(acc[2], aL0, aL1, aL2, aL3, h10, h11);
                MMA_BF16(acc[3], aL0, aL1, aL2, aL3, h12, h13);
            }

            // ---- epilogue (R7-verified frag->col map) ----
            const int row0 = m0 + mrow0 + g;
            const int row1 = row0 + 8;
            #pragma unroll
            for (int f = 0; f < 4; f++) {
                const int cloc = ncol0 + ((f & 1) ? 8 : 0) + ((f >> 1) ? 16 : 0) + tg * 2;
                const float b0 = bias_sm[cloc];
                const float b1 = bias_sm[cloc + 1];
                if (row0 < n) {
                    float* p = out + (size_t)list[row0] * OUT_CH + colBase + cloc;
                    *(float2*)p = make_float2(acc[f][0] + b0, acc[f][1] + b1);
                }
                if (row1 < n) {
                    float* p = out + (size_t)list[row1] * OUT_CH + colBase + cloc;
                    *(float2*)p = make_float2(acc[f][2] + b0, acc[f][3] + b1);
                }
            }
        }
        __syncthreads();   // k-loop reads done before next tile's STS
    }
}

// ================= launch ==================================================
extern "C" void kernel_launch(void* const* d_in, const int* in_sizes, int n_in,
                              void* d_out, int out_size) {
    const float* inputs   = (const float*)d_in[0];
    const int*   task_ids = (const int*)d_in[1];   // JAX x64 disabled -> int32
    const float* te       = (const float*)d_in[2];
    float*       out      = (float*)d_out;
    int B = in_sizes[1];

    cudaFuncSetAttribute(affine_hmma_kernel,
                         cudaFuncAttributeMaxDynamicSharedMemorySize, SMEM_B);
    dim3 grid(OUT_CH / NCOLS, NTASKS, 1);   // (2, 64) = 128 CTAs, single launch
    affine_hmma_kernel<<<grid, THREADS, SMEM_B>>>(inputs, task_ids, te, out, B);
}

// round 15
// speedup vs baseline: 1.1631x; 1.1631x over previous
#include <cuda_runtime.h>
#include <cuda_bf16.h>
#include <cstdint>

#define IN_CH   256
#define OUT_CH  256
#define NTASKS  64
#define WSIZE   (OUT_CH * IN_CH)
#define FULL_EMBED (WSIZE + OUT_CH)
#define BMAX    4096
#define NCOLS   128             // output cols per CTA
#define MT      64              // rows per M-tile
#define THREADS 512
#define SCAN_IT (BMAX / THREADS)   // 8

// bf16 row stride: 264 elements = 528 bytes (conflict-free ldmatrix phases)
#define RSTRIDE_B 528

// smem byte offsets
#define SM_WHI  0
#define SM_WLO  (SM_WHI + NCOLS * RSTRIDE_B)        // 67584
#define SM_XHI  (SM_WLO + NCOLS * RSTRIDE_B)        // 135168
#define SM_XLO  (SM_XHI + MT * RSTRIDE_B)           // 168960
#define SM_BIAS (SM_XLO + MT * RSTRIDE_B)           // 202752
#define SM_LIST (SM_BIAS + NCOLS * 4)               // 203264 (uint16 x 4096)
#define SM_CNT  (SM_LIST + BMAX * 2)                // 211456
#define SMEM_B  (SM_CNT + 16)                       // ~206.5KB, 1 CTA/SM

// ================= helpers =================================================
__device__ __forceinline__ uint32_t smem_u32(const void* p) {
    uint32_t a;
    asm("{ .reg .u64 t; cvta.to.shared.u64 t, %1; cvt.u32.u64 %0, t; }" : "=r"(a) : "l"(p));
    return a;
}
__device__ __forceinline__ uint32_t pack_bf16(float a, float b) {
    __nv_bfloat162 t = __floats2bfloat162_rn(a, b);
    return *(uint32_t*)&t;
}
__device__ __forceinline__ float bf_hi(float x) {
    return __bfloat162float(__float2bfloat16(x));
}

#define LDSM_X4(r0, r1, r2, r3, addr)                                      \
    asm volatile("ldmatrix.sync.aligned.m8n8.x4.shared.b16 {%0,%1,%2,%3}, [%4];" \
        : "=r"(r0), "=r"(r1), "=r"(r2), "=r"(r3) : "r"(addr))

#define MMA_BF16(c, a0, a1, a2, a3, b0, b1)                                \
    asm volatile("mma.sync.aligned.m16n8k16.row.col.f32.bf16.bf16.f32 "    \
        "{%0,%1,%2,%3}, {%4,%5,%6,%7}, {%8,%9}, {%0,%1,%2,%3};"            \
        : "+f"((c)[0]), "+f"((c)[1]), "+f"((c)[2]), "+f"((c)[3])           \
        : "r"(a0), "r"(a1), "r"(a2), "r"(a3), "r"(b0), "r"(b1))

// W convert+STS for one 4-col batch of this warp
__device__ __forceinline__ void w_sts(char* smem, int c, int lane,
                                      float4 a, float4 b) {
    char* whi = smem + SM_WHI + c * RSTRIDE_B;
    char* wlo = smem + SM_WLO + c * RSTRIDE_B;
    *(uint2*)(whi + lane * 8) =
        make_uint2(pack_bf16(a.x, a.y), pack_bf16(a.z, a.w));
    *(uint2*)(whi + 256 + lane * 8) =
        make_uint2(pack_bf16(b.x, b.y), pack_bf16(b.z, b.w));
    *(uint2*)(wlo + lane * 8) =
        make_uint2(pack_bf16(a.x - bf_hi(a.x), a.y - bf_hi(a.y)),
                   pack_bf16(a.z - bf_hi(a.z), a.w - bf_hi(a.w)));
    *(uint2*)(wlo + 256 + lane * 8) =
        make_uint2(pack_bf16(b.x - bf_hi(b.x), b.y - bf_hi(b.y)),
                   pack_bf16(b.z - bf_hi(b.z), b.w - bf_hi(b.w)));
}

// ================= main: CTA = (task, 128-col chunk), fused scan ===========
__global__ __launch_bounds__(THREADS, 1)
void affine_hmma_kernel(const float* __restrict__ inputs,
                        const int* __restrict__ task_ids,
                        const float* __restrict__ te,
                        float* __restrict__ out,
                        int B) {
    extern __shared__ char smem[];
    const uint32_t sb = smem_u32(smem);
    float* bias_sm = (float*)(smem + SM_BIAS);
    unsigned short* list = (unsigned short*)(smem + SM_LIST);
    int* s_n = (int*)(smem + SM_CNT);

    const int task    = blockIdx.y;
    const int colBase = blockIdx.x * NCOLS;
    const int tid     = threadIdx.x;
    const int lane    = tid & 31;
    const int wid     = tid >> 5;      // 0..15

    if (tid == 0) s_n[0] = 0;
    __syncthreads();

    const float* emb = te + (size_t)task * FULL_EMBED;

    // ---- W batch 1: issue 8 LDG.128 (cols w, w+16, w+32, w+48) ----
    float4 wa0[4], wa1[4];
    #pragma unroll
    for (int rr = 0; rr < 4; rr++) {
        const int c = wid + rr * 16;
        const float4* wg = (const float4*)(emb + (size_t)(colBase + c) * IN_CH);
        wa0[rr] = wg[lane];
        wa1[rr] = wg[lane + 32];
    }

    // ---- scan: batch ids, all ballots, ONE atomic per warp ----
    {
        int myid[SCAN_IT];
        #pragma unroll
        for (int j = 0; j < SCAN_IT; j++) {
            const int i = tid + j * THREADS;
            myid[j] = (i < B) ? task_ids[i] : -1;
        }
        unsigned bal[SCAN_IT];
        int wtot = 0;
        #pragma unroll
        for (int j = 0; j < SCAN_IT; j++) {
            bal[j] = __ballot_sync(0xFFFFFFFFu, myid[j] == task);
            wtot += __popc(bal[j]);
        }
        int base = 0;
        if (lane == 0 && wtot) base = atomicAdd(s_n, wtot);
        base = __shfl_sync(0xFFFFFFFFu, base, 0);
        #pragma unroll
        for (int j = 0; j < SCAN_IT; j++) {
            if (myid[j] == task) {
                const int pos = base + __popc(bal[j] & ((1u << lane) - 1u));
                list[pos] = (unsigned short)(tid + j * THREADS);
            }
            base += __popc(bal[j]);
        }
    }

    // ---- bias ----
    if (tid < NCOLS) bias_sm[tid] = emb[WSIZE + colBase + tid];

    // ---- W batch 2 issue, convert batch 1, convert batch 2 ----
    {
        float4 wb0[4], wb1[4];
        #pragma unroll
        for (int rr = 0; rr < 4; rr++) {
            const int c = wid + (rr + 4) * 16;        // cols w+64 .. w+112
            const float4* wg = (const float4*)(emb + (size_t)(colBase + c) * IN_CH);
            wb0[rr] = wg[lane];
            wb1[rr] = wg[lane + 32];
        }
        #pragma unroll
        for (int rr = 0; rr < 4; rr++)
            w_sts(smem, wid + rr * 16, lane, wa0[rr], wa1[rr]);
        #pragma unroll
        for (int rr = 0; rr < 4; rr++)
            w_sts(smem, wid + (rr + 4) * 16, lane, wb0[rr], wb1[rr]);
    }
    __syncthreads();
    const int n = s_n[0];

    // ---- warp tiling: 4 (M) x 4 (N); warp = m16 x n32 (R7-verified maps) ----
    const int warp_m = wid >> 2;          // 0..3
    const int warp_n = wid & 3;           // 0..3
    const int mrow0  = warp_m * 16;
    const int ncol0  = warp_n * 32;
    const int g      = lane >> 2;
    const int tg     = lane & 3;

    const int a_row  = mrow0 + ((lane >> 3) & 1) * 8 + (lane & 7);
    const uint32_t a_off = (uint32_t)a_row * RSTRIDE_B + ((lane >> 4) * 16);
    const int b_col0 = ncol0 + (lane >> 4) * 8 + (lane & 7);
    const uint32_t b_koff = ((lane >> 3) & 1) * 16;
    const uint32_t bh0 = sb + SM_WHI + (uint32_t)b_col0 * RSTRIDE_B + b_koff;
    const uint32_t bh1 = bh0 + 16 * RSTRIDE_B;
    const uint32_t bl0 = bh0 + (SM_WLO - SM_WHI);
    const uint32_t bl1 = bh1 + (SM_WLO - SM_WHI);
    const uint32_t ahi = sb + SM_XHI + a_off;
    const uint32_t alo = sb + SM_XLO + a_off;

    // ---- loop over 64-row tiles ----
    for (int m0 = 0; m0 < n; m0 += MT) {
        if (m0) __syncthreads();

        // stage X hi/lo: each warp 4 rows; valid rows only (stale data masked)
        {
            float4 v0[4], v1[4];
            int nv = 0;
            #pragma unroll
            for (int rr = 0; rr < 4; rr++) {
                const int row = m0 + wid * 4 + rr;
                if (row < n) {
                    const float4* xg =
                        (const float4*)(inputs + (size_t)list[row] * IN_CH);
                    v0[rr] = xg[lane];
                    v1[rr] = xg[lane + 32];
                    nv = rr + 1;
                }
            }
            for (int rr = 0; rr < nv; rr++) {
                const int r = wid * 4 + rr;
                char* xhi = smem + SM_XHI + r * RSTRIDE_B;
                char* xlo = smem + SM_XLO + r * RSTRIDE_B;
                float4 a = v0[rr], b = v1[rr];
                *(uint2*)(xhi + lane * 8) =
                    make_uint2(pack_bf16(a.x, a.y), pack_bf16(a.z, a.w));
                *(uint2*)(xhi + 256 + lane * 8) =
                    make_uint2(pack_bf16(b.x, b.y), pack_bf16(b.z, b.w));
                *(uint2*)(xlo + lane * 8) =
                    make_uint2(pack_bf16(a.x - bf_hi(a.x), a.y - bf_hi(a.y)),
                               pack_bf16(a.z - bf_hi(a.z), a.w - bf_hi(a.w)));
                *(uint2*)(xlo + 256 + lane * 8) =
                    make_uint2(pack_bf16(b.x - bf_hi(b.x), b.y - bf_hi(b.y)),
                               pack_bf16(b.z - bf_hi(b.z), b.w - bf_hi(b.w)));
            }
        }
        __syncthreads();

        // warp-level tail skip
        if (m0 + mrow0 < n) {
            float acc[4][4];
            #pragma unroll
            for (int f = 0; f < 4; f++)
                #pragma unroll
                for (int j = 0; j < 4; j++) acc[f][j] = 0.f;

            #pragma unroll 4
            for (int ks = 0; ks < IN_CH; ks += 16) {
                const uint32_t kb = ks * 2;
                uint32_t aH0, aH1, aH2, aH3, aL0, aL1, aL2, aL3;
                uint32_t h00, h01, h02, h03, h10, h11, h12, h13;
                uint32_t l00, l01, l02, l03, l10, l11, l12, l13;
                LDSM_X4(aH0, aH1, aH2, aH3, ahi + kb);
                LDSM_X4(aL0, aL1, aL2, aL3, alo + kb);
                LDSM_X4(h00, h01, h02, h03, bh0 + kb);
                LDSM_X4(h10, h11, h12, h13, bh1 + kb);
                LDSM_X4(l00, l01, l02, l03, bl0 + kb);
                LDSM_X4(l10, l11, l12, l13, bl1 + kb);
                MMA_BF16(acc[0], aH0, aH1, aH2, aH3, h00, h01);
                MMA_BF16(acc[1], aH0, aH1, aH2, aH3, h02, h03);
                MMA_BF16(acc[2], aH0, aH1, aH2, aH3, h10, h11);
                MMA_BF16(acc[3], aH0, aH1, aH2, aH3, h12, h13);
                MMA_BF16(acc[0], aH0, aH1, aH2, aH3, l00, l01);
                MMA_BF16(acc[1], aH0, aH1, aH2, aH3, l02, l03);
                MMA_BF16(acc[2], aH0, aH1, aH2, aH3, l10, l11);
                MMA_BF16(acc[3], aH0, aH1, aH2, aH3, l12, l13);
                MMA_BF16(acc[0], aL0, aL1, aL2, aL3, h00, h01);
                MMA_BF16(acc[1], aL0, aL1, aL2, aL3, h02, h03);
                MMA_BF16(acc[2], aL0, aL1, aL2, aL3, h10, h11);
                MMA_BF16(acc[3], aL0, aL1, aL2, aL3, h12, h13);
            }

            // ---- epilogue (R7-verified frag->col map) ----
            const int row0 = m0 + mrow0 + g;
            const int row1 = row0 + 8;
            #pragma unroll
            for (int f = 0; f < 4; f++) {
                const int cloc = ncol0 + ((f & 1) ? 8 : 0) + ((f >> 1) ? 16 : 0) + tg * 2;
                const float b0 = bias_sm[cloc];
                const float b1 = bias_sm[cloc + 1];
                if (row0 < n) {
                    float* p = out + (size_t)list[row0] * OUT_CH + colBase + cloc;
                    *(float2*)p = make_float2(acc[f][0] + b0, acc[f][1] + b1);
                }
                if (row1 < n) {
                    float* p = out + (size_t)list[row1] * OUT_CH + colBase + cloc;
                    *(float2*)p = make_float2(acc[f][2] + b0, acc[f][3] + b1);
                }
            }
        }
    }
}

// ================= launch ==================================================
extern "C" void kernel_launch(void* const* d_in, const int* in_sizes, int n_in,
                              void* d_out, int out_size) {
    const float* inputs   = (const float*)d_in[0];
    const int*   task_ids = (const int*)d_in[1];   // JAX x64 disabled -> int32
    const float* te       = (const float*)d_in[2];
    float*       out      = (float*)d_out;
    int B = in_sizes[1];

    cudaFuncSetAttribute(affine_hmma_kernel,
                         cudaFuncAttributeMaxDynamicSharedMemorySize, SMEM_B);
    dim3 grid(OUT_CH / NCOLS, NTASKS, 1);   // (2, 64) = 128 CTAs, single launch
    affine_hmma_kernel<<<grid, THREADS, SMEM_B>>>(inputs, task_ids, te, out, B);
}